// round 8
// baseline (speedup 1.0000x reference)
#include <cuda_runtime.h>
#include <cuda_bf16.h>
#include <cstdint>

#define NB 512
#define NH 256
#define NT 128
#define NCTA 128

// ---------------- device scratch ----------------
__device__ __align__(128) float g_Hdec[NT*NB*NH];
__device__ __align__(128) __nv_bfloat16 g_A0h[NB*NH], g_A0l[NB*NH];
__device__ __align__(128) __nv_bfloat16 g_A1h[NB*NH], g_A1l[NB*NH];
__device__ __align__(128) __nv_bfloat16 g_Xh[256*NB*64], g_Xl[256*NB*64];
// B fragment order per jt: [part(2)][chunk(NCH)][ng(8)][lane(32)][reg(2)] u32
__device__ __align__(128) uint32_t g_eB[16*20480];      // NCH=20 (enc: Whh + Wih)
__device__ __align__(128) uint32_t g_d0B[16*20480];     // NCH=20 (dec step0: dWhh + dWih)
__device__ __align__(128) uint32_t g_dB[16*16384];      // NCH=16 (dec folded)
__device__ __align__(128) float g_Wcomb[768*256];       // reg fold temp
__device__ float g_bias_enc[1024], g_bias_dec[1024], g_bias_dec0[1024];
__device__ float g_regWT[256*64];
__device__ __align__(128) unsigned g_flags[8*32];       // per-mt group: 16 flags in one 128B line

// ---------------- prep helpers ----------------
__device__ __forceinline__ uint32_t pack_split(float v0, float v1, int part) {
    __nv_bfloat16 h0 = __float2bfloat16(v0), h1 = __float2bfloat16(v1);
    if (part == 0)
        return (uint32_t)__bfloat16_as_ushort(h0) | ((uint32_t)__bfloat16_as_ushort(h1) << 16);
    __nv_bfloat16 l0 = __float2bfloat16(v0 - __bfloat162float(h0));
    __nv_bfloat16 l1 = __float2bfloat16(v1 - __bfloat162float(h1));
    return (uint32_t)__bfloat16_as_ushort(l0) | ((uint32_t)__bfloat16_as_ushort(l1) << 16);
}

__device__ __forceinline__ float gru_w(const float* Wih, const float* Whh,
                                       int sec, int j, int k) {
    if (k < 256) {
        if (sec == 0) return Whh[j*256 + k];
        if (sec == 1) return Whh[(256 + j)*256 + k];
        if (sec == 3) return Whh[(512 + j)*256 + k];
        return 0.f;
    } else {
        int f = k - 256;
        if (sec == 0) return Wih[j*64 + f];
        if (sec == 1) return Wih[(256 + j)*64 + f];
        if (sec == 2) return Wih[(512 + j)*64 + f];
        return 0.f;
    }
}

__global__ void k_fold(const float* __restrict__ dWih, const float* __restrict__ rW)
{
    int n = blockIdx.x;
    int k = threadIdx.x;
    float s = 0.f;
    #pragma unroll
    for (int f = 0; f < 64; f++) s += rW[f*256 + k] * dWih[n*64 + f];
    g_Wcomb[n*256 + k] = s;
}

__global__ void k_prep_frag(const float* __restrict__ eWih, const float* __restrict__ eWhh,
                            const float* __restrict__ dWih, const float* __restrict__ dWhh)
{
    const int stride = gridDim.x * blockDim.x;
    const int t0 = blockIdx.x * blockDim.x + threadIdx.x;

    for (int i = t0; i < 16*20480; i += stride) {
        int jt = i / 20480, rem = i % 20480;
        int part = rem / 10240; rem %= 10240;
        int ch = rem / 512;     rem %= 512;
        int ng = rem / 64;      rem %= 64;
        int lane = rem >> 1, r = rem & 1;
        int k  = ch*16 + (lane & 3)*2 + r*8;
        int nl = ng*8 + (lane >> 2);
        int sec = nl & 3, j = jt*16 + (nl >> 2);
        g_eB[i]  = pack_split(gru_w(eWih, eWhh, sec, j, k), gru_w(eWih, eWhh, sec, j, k+1), part);
        g_d0B[i] = pack_split(gru_w(dWih, dWhh, sec, j, k), gru_w(dWih, dWhh, sec, j, k+1), part);
    }

    for (int i = t0; i < 16*16384; i += stride) {
        int jt = i / 16384, rem = i % 16384;
        int part = rem / 8192; rem %= 8192;
        int ch = rem / 512;    rem %= 512;
        int ng = rem / 64;     rem %= 64;
        int lane = rem >> 1, r = rem & 1;
        int k  = ch*16 + (lane & 3)*2 + r*8;
        int nl = ng*8 + (lane >> 2);
        int sec = nl & 3, j = jt*16 + (nl >> 2);
        float v0, v1;
        if (sec == 3) {
            v0 = dWhh[(512 + j)*256 + k];
            v1 = dWhh[(512 + j)*256 + k + 1];
        } else {
            int n = sec*256 + j;
            v0 = g_Wcomb[n*256 + k]     + ((sec < 2) ? dWhh[n*256 + k]     : 0.f);
            v1 = g_Wcomb[n*256 + k + 1] + ((sec < 2) ? dWhh[n*256 + k + 1] : 0.f);
        }
        g_dB[i] = pack_split(v0, v1, part);
    }
}

__global__ void k_prep_x(const float* __restrict__ x)
{
    const int stride = gridDim.x * blockDim.x;
    for (int i = blockIdx.x * blockDim.x + threadIdx.x; i < 256*512*64; i += stride) {
        int t = i / (512*64); int rem = i - t*512*64;
        int m = rem >> 6, f = rem & 63;
        float v = x[(m*256 + t)*64 + f];
        __nv_bfloat16 hb = __float2bfloat16(v);
        g_Xh[i] = hb;
        g_Xl[i] = __float2bfloat16(v - __bfloat162float(hb));
    }
}

__global__ void k_prep_bias(const float* __restrict__ ebih, const float* __restrict__ ebhh,
                            const float* __restrict__ dWih,
                            const float* __restrict__ dbih, const float* __restrict__ dbhh,
                            const float* __restrict__ rW,   const float* __restrict__ rb)
{
    const int stride = gridDim.x * blockDim.x;
    const int t0 = blockIdx.x * blockDim.x + threadIdx.x;
    for (int i = t0; i < 256*64; i += stride) {
        int k = i >> 6, f = i & 63;
        g_regWT[i] = rW[f*256 + k];
    }
    for (int i = t0; i < 1024; i += stride) {
        int sec = i >> 8, j = i & 255;
        float be, bd0, bd;
        if (sec <= 1) {
            int n = sec*256 + j;
            be  = ebih[n] + ebhh[n];
            bd0 = dbih[n] + dbhh[n];
            float bc = dbih[n];
            for (int f = 0; f < 64; f++) bc += rb[f]*dWih[n*64 + f];
            bd = bc + dbhh[n];
        } else if (sec == 2) {
            int n = 512 + j;
            be = ebih[n]; bd0 = dbih[n];
            float bc = dbih[n];
            for (int f = 0; f < 64; f++) bc += rb[f]*dWih[n*64 + f];
            bd = bc;
        } else {
            int n = 512 + j;
            be = ebhh[n]; bd0 = dbhh[n]; bd = dbhh[n];
        }
        g_bias_enc[i] = be; g_bias_dec0[i] = bd0; g_bias_dec[i] = bd;
    }
}

__global__ void k_reset() { if (threadIdx.x < 256) g_flags[threadIdx.x] = 0u; }

// ---------------- persistent fused GRU recurrence ----------------
#define ASTRIDE 328                     // A smem row stride in bf16 (pad 8)
#define APS (64*ASTRIDE*2)              // 41984 bytes per precision part
#define SB_OFF   (2*APS)                // 83968
#define SHOLD_OFF (SB_OFF + 81920)      // 165888
#define SMEM_BYTES (SHOLD_OFF + 4096)   // 169984

#define MMA16816(d, a, b0, b1) \
    asm volatile("mma.sync.aligned.m16n8k16.row.col.f32.bf16.bf16.f32 " \
        "{%0,%1,%2,%3},{%4,%5,%6,%7},{%8,%9},{%0,%1,%2,%3};" \
        : "+f"((d)[0]), "+f"((d)[1]), "+f"((d)[2]), "+f"((d)[3]) \
        : "r"((a)[0]), "r"((a)[1]), "r"((a)[2]), "r"((a)[3]), "r"(b0), "r"(b1))

#define LDSM4(a, addr) \
    asm volatile("ldmatrix.sync.aligned.m8n8.x4.shared.b16 {%0,%1,%2,%3}, [%4];" \
        : "=r"((a)[0]), "=r"((a)[1]), "=r"((a)[2]), "=r"((a)[3]) : "r"(addr))

// A fragments via ldmatrix.x4; B via LDS.64 pairs.
template<int NCH>
__device__ __forceinline__ void mma_chunks(uint32_t aAddr0, const uint32_t* sBu,
                                           float acc[2][2][4], int wn, int lane)
{
    #pragma unroll 4
    for (int ch = 0; ch < NCH; ch++) {
        uint32_t ah[2][4], al[2][4];
        #pragma unroll
        for (int mi = 0; mi < 2; mi++) {
            uint32_t ad = aAddr0 + mi*(16*ASTRIDE*2) + ch*32;
            LDSM4(ah[mi], ad);
            LDSM4(al[mi], ad + APS);
        }
        #pragma unroll
        for (int ni = 0; ni < 2; ni++) {
            const int ng = wn*2 + ni;
            const uint32_t* bp = sBu + ((ch*8 + ng)*32 + lane)*2;
            uint2 bh = *(const uint2*)bp;
            uint2 bl = *(const uint2*)(bp + NCH*512);
            #pragma unroll
            for (int mi = 0; mi < 2; mi++) {
                MMA16816(acc[mi][ni], ah[mi], bh.x, bh.y);
                MMA16816(acc[mi][ni], ah[mi], bl.x, bl.y);
                MMA16816(acc[mi][ni], al[mi], bh.x, bh.y);
            }
        }
    }
}

__global__ __launch_bounds__(256, 1) void k_persist(
    const __nv_bfloat16* __restrict__ Xh, const __nv_bfloat16* __restrict__ Xl,
    const uint4* __restrict__ eB, const uint4* __restrict__ d0B, const uint4* __restrict__ dB,
    const float* __restrict__ be, const float* __restrict__ bd0, const float* __restrict__ bd,
    float* __restrict__ Hdec,
    __nv_bfloat16* __restrict__ A0h, __nv_bfloat16* __restrict__ A0l,
    __nv_bfloat16* __restrict__ A1h, __nv_bfloat16* __restrict__ A1l)
{
    extern __shared__ char sm[];
    const int tid = threadIdx.x;
    const int bid = blockIdx.x;
    const int mt = bid & 7;
    const int jt = bid >> 3;
    const int m0 = mt*64;

    uint4* sA4h = (uint4*)sm;
    uint4* sA4l = (uint4*)(sm + APS);
    uint4* sB4  = (uint4*)(sm + SB_OFF);
    float* sHold = (float*)(sm + SHOLD_OFF);
    const uint32_t* sBu = (const uint32_t*)(sm + SB_OFF);

    const int lane = tid & 31;
    const int wid  = tid >> 5;
    const int wm = wid & 1, wn = wid >> 1;
    const int qr = lane >> 2, qp = lane & 3;

    const uint32_t sAu = (uint32_t)__cvta_generic_to_shared(sm);
    const uint32_t aAddr0 = sAu + ((wm*32 + (lane & 15))*ASTRIDE + (lane >> 4)*8)*2;

    volatile unsigned* flags = g_flags;

    for (int i = tid; i < 1024; i += 256) sHold[i] = 0.f;

    for (int s = 0; s < 256; s++) {
        // ---- B phase load (3 times total) ----
        if (s == 0 || s == 128 || s == 129) {
            const uint4* Bsrc;
            int nB;
            if (s == 0)        { Bsrc = eB  + (size_t)jt * (20*256); nB = 20*256; }
            else if (s == 128) { Bsrc = d0B + (size_t)jt * (20*256); nB = 20*256; }
            else               { Bsrc = dB  + (size_t)jt * (16*256); nB = 16*256; }
            for (int i = tid; i < nB; i += 256) sB4[i] = Bsrc[i];
        }

        // ---- A stage (prev step's h as bf16 hi/lo) ----
        if (s == 0) {
            uint4 z = make_uint4(0, 0, 0, 0);
            #pragma unroll
            for (int i = tid; i < 2048; i += 256) {
                int r = i >> 5, c = i & 31;
                sA4h[r*41 + c] = z;
                sA4l[r*41 + c] = z;
            }
        } else {
            const uint4* Ah4 = (const uint4*)(((s - 1) & 1) ? A1h : A0h);
            const uint4* Al4 = (const uint4*)(((s - 1) & 1) ? A1l : A0l);
            #pragma unroll
            for (int i = tid; i < 2048; i += 256) {
                int r = i >> 5, c = i & 31;
                sA4h[r*41 + c] = Ah4[(m0 + r)*32 + c];
                sA4l[r*41 + c] = Al4[(m0 + r)*32 + c];
            }
        }
        // ---- X stage (encoder steps + decoder step 0 uses x127) ----
        if (s <= 128) {
            int t = (s < 128) ? s : 127;
            const uint4* Xh4 = (const uint4*)(Xh + (size_t)t*NB*64);
            const uint4* Xl4 = (const uint4*)(Xl + (size_t)t*NB*64);
            #pragma unroll
            for (int i = tid; i < 512; i += 256) {
                int r = i >> 3, c = i & 7;
                sA4h[r*41 + 32 + c] = Xh4[(m0 + r)*8 + c];
                sA4l[r*41 + 32 + c] = Xl4[(m0 + r)*8 + c];
            }
        }
        __syncthreads();

        // ---- 3-pass split-bf16 MMA ----
        float acc[2][2][4];
        #pragma unroll
        for (int a = 0; a < 2; a++)
            #pragma unroll
            for (int b = 0; b < 2; b++)
                #pragma unroll
                for (int c = 0; c < 4; c++) acc[a][b][c] = 0.f;

        if (s <= 128) mma_chunks<20>(aAddr0, sBu, acc, wn, lane);
        else          mma_chunks<16>(aAddr0, sBu, acc, wn, lane);

        const float* bias = (s < 128) ? be : ((s == 128) ? bd0 : bd);

        // ---- fused GRU epilogue; h tile persists in sHold ----
        #pragma unroll
        for (int mi = 0; mi < 2; mi++) {
            #pragma unroll
            for (int ni = 0; ni < 2; ni++) {
                float d0 = acc[mi][ni][0], d1 = acc[mi][ni][1];
                float d2 = acc[mi][ni][2], d3 = acc[mi][ni][3];
                float e0 = __shfl_xor_sync(0xffffffffu, d0, 1);
                float e1 = __shfl_xor_sync(0xffffffffu, d1, 1);
                float e2 = __shfl_xor_sync(0xffffffffu, d2, 1);
                float e3 = __shfl_xor_sync(0xffffffffu, d3, 1);
                if ((qp & 1) == 0) {
                    const int jloc = wn*4 + ni*2 + (qp >> 1);
                    const int j = jt*16 + jloc;
                    const float b0 = bias[j], b1 = bias[256 + j];
                    const float b2 = bias[512 + j], b3 = bias[768 + j];
                    #pragma unroll
                    for (int hf = 0; hf < 2; hf++) {
                        const int mloc = wm*32 + mi*16 + qr + hf*8;
                        float ga = (hf ? d2 : d0) + b0;
                        float gb = (hf ? d3 : d1) + b1;
                        float gc = (hf ? e2 : e0) + b2;
                        float gd = (hf ? e3 : e1) + b3;
                        float rg = 1.f/(1.f + __expf(-ga));
                        float zg = 1.f/(1.f + __expf(-gb));
                        float nn = tanhf(fmaf(rg, gd, gc));
                        float hv = (1.f - zg)*nn + zg*sHold[mloc*16 + jloc];
                        sHold[mloc*16 + jloc] = hv;
                    }
                }
            }
        }
        __syncthreads();

        // ---- outputs: bf16 hi/lo A for next step; fp32 Hdec for decoder ----
        __nv_bfloat16* obh = (s & 1) ? A1h : A0h;
        __nv_bfloat16* obl = (s & 1) ? A1l : A0l;
        if (tid < 64) {
            int r = tid;
            union { uint4 v; ushort u[8]; } ph[2], pl[2];
            #pragma unroll
            for (int c = 0; c < 16; c++) {
                float f = sHold[r*16 + c];
                __nv_bfloat16 hb = __float2bfloat16(f);
                __nv_bfloat16 lb = __float2bfloat16(f - __bfloat162float(hb));
                ph[c >> 3].u[c & 7] = __bfloat16_as_ushort(hb);
                pl[c >> 3].u[c & 7] = __bfloat16_as_ushort(lb);
            }
            uint4* dh = (uint4*)(obh + (size_t)(m0 + r)*256 + jt*16);
            uint4* dl = (uint4*)(obl + (size_t)(m0 + r)*256 + jt*16);
            dh[0] = ph[0].v; dh[1] = ph[1].v;
            dl[0] = pl[0].v; dl[1] = pl[1].v;
        }
        if (s >= 128) {
            int r = tid >> 2, c = tid & 3;
            float4 v = make_float4(sHold[r*16 + c*4], sHold[r*16 + c*4 + 1],
                                   sHold[r*16 + c*4 + 2], sHold[r*16 + c*4 + 3]);
            *(float4*)&Hdec[(size_t)(s - 128)*NB*NH + (size_t)(m0 + r)*256 + jt*16 + c*4] = v;
        }
        __syncthreads();

        // ---- mt-scoped hierarchical barrier (atomic-free) ----
        // Release: cumulative fence by tid0 (after bar.sync -> covers all threads'
        // stores) then plain flag store. Acquire: 16 threads poll the group's 16
        // flags (one 128B line), fence, bar.sync.
        if (tid == 0) {
            __threadfence();
            flags[mt*32 + jt] = (unsigned)(s + 1);
        }
        if (tid < 16) {
            volatile unsigned* f = &flags[mt*32 + tid];
            while (*f < (unsigned)(s + 1)) {}
            __threadfence();
        }
        __syncthreads();
    }
}

// ---------------- final projection ----------------
__global__ __launch_bounds__(256) void k_out(const float* __restrict__ Hdec,
                                             const float* __restrict__ regWT,
                                             const float* __restrict__ rb,
                                             float* __restrict__ out)
{
    __shared__ float hs[32][260];
    const int tid = threadIdx.x;
    const int r0 = blockIdx.x * 32;
    #pragma unroll
    for (int i = 0; i < 8; i++) {
        int g = i*256 + tid; int row = g >> 6, kq = g & 63;
        *(float4*)&hs[row][kq*4] = *(const float4*)(Hdec + (size_t)(r0 + row)*256 + kq*4);
    }
    __syncthreads();
    const int row = tid >> 3;
    const int f0 = (tid & 7)*8;
    float acc[8];
    #pragma unroll
    for (int q = 0; q < 8; q++) acc[q] = rb[f0 + q];
    for (int k = 0; k < 256; k++) {
        float hvv = hs[row][k];
        float4 w0 = *(const float4*)(regWT + k*64 + f0);
        float4 w1 = *(const float4*)(regWT + k*64 + f0 + 4);
        acc[0] += hvv*w0.x; acc[1] += hvv*w0.y; acc[2] += hvv*w0.z; acc[3] += hvv*w0.w;
        acc[4] += hvv*w1.x; acc[5] += hvv*w1.y; acc[6] += hvv*w1.z; acc[7] += hvv*w1.w;
    }
    int rr = r0 + row;
    int b = rr & 511;
    int t = rr >> 9;
    float* o = out + ((size_t)b*128 + t)*64 + f0;
    #pragma unroll
    for (int q = 0; q < 8; q++) o[q] = acc[q];
}

// ---------------- launch ----------------
extern "C" void kernel_launch(void* const* d_in, const int* in_sizes, int n_in,
                              void* d_out, int out_size)
{
    (void)in_sizes; (void)n_in; (void)out_size;
    const float* x    = (const float*)d_in[0];
    const float* eWih = (const float*)d_in[1];
    const float* eWhh = (const float*)d_in[2];
    const float* ebih = (const float*)d_in[3];
    const float* ebhh = (const float*)d_in[4];
    const float* dWih = (const float*)d_in[5];
    const float* dWhh = (const float*)d_in[6];
    const float* dbih = (const float*)d_in[7];
    const float* dbhh = (const float*)d_in[8];
    const float* rW   = (const float*)d_in[9];
    const float* rb   = (const float*)d_in[10];
    float* out = (float*)d_out;

    float *pHdec, *pBe, *pBd, *pBd0, *pWT;
    __nv_bfloat16 *pA0h, *pA0l, *pA1h, *pA1l, *pXh, *pXl;
    uint32_t *peB, *pd0B, *pdB;
    cudaGetSymbolAddress((void**)&pHdec, g_Hdec);
    cudaGetSymbolAddress((void**)&pA0h, g_A0h);
    cudaGetSymbolAddress((void**)&pA0l, g_A0l);
    cudaGetSymbolAddress((void**)&pA1h, g_A1h);
    cudaGetSymbolAddress((void**)&pA1l, g_A1l);
    cudaGetSymbolAddress((void**)&pXh, g_Xh);
    cudaGetSymbolAddress((void**)&pXl, g_Xl);
    cudaGetSymbolAddress((void**)&peB, g_eB);
    cudaGetSymbolAddress((void**)&pd0B, g_d0B);
    cudaGetSymbolAddress((void**)&pdB, g_dB);
    cudaGetSymbolAddress((void**)&pBe, g_bias_enc);
    cudaGetSymbolAddress((void**)&pBd, g_bias_dec);
    cudaGetSymbolAddress((void**)&pBd0, g_bias_dec0);
    cudaGetSymbolAddress((void**)&pWT, g_regWT);

    cudaFuncSetAttribute(k_persist, cudaFuncAttributeMaxDynamicSharedMemorySize, SMEM_BYTES);

    k_fold<<<768, 256>>>(dWih, rW);
    k_prep_frag<<<512, 256>>>(eWih, eWhh, dWih, dWhh);
    k_prep_x<<<2048, 256>>>(x);
    k_prep_bias<<<128, 256>>>(ebih, ebhh, dWih, dbih, dbhh, rW, rb);
    k_reset<<<1, 256>>>();

    k_persist<<<NCTA, 256, SMEM_BYTES>>>(
        pXh, pXl,
        (const uint4*)peB, (const uint4*)pd0B, (const uint4*)pdB,
        pBe, pBd0, pBd,
        pHdec, pA0h, pA0l, pA1h, pA1l);

    k_out<<<(NB*NT)/32, 256>>>(pHdec, pWT, rb, out);
}

// round 9
// speedup vs baseline: 1.4784x; 1.4784x over previous
#include <cuda_runtime.h>
#include <cuda_bf16.h>
#include <cstdint>

#define NB 512
#define NH 256
#define NT 128
#define NCTA 128

// ---------------- device scratch ----------------
__device__ __align__(128) float g_Hdec[NT*NB*NH];
__device__ __align__(128) __nv_bfloat16 g_A0h[NB*NH], g_A0l[NB*NH];
__device__ __align__(128) __nv_bfloat16 g_A1h[NB*NH], g_A1l[NB*NH];
__device__ __align__(128) __nv_bfloat16 g_Xh[256*NB*64], g_Xl[256*NB*64];
// B fragment order per jt: [part(2)][chunk(NCH)][ng(8)][lane(32)][reg(2)] u32
__device__ __align__(128) uint32_t g_eB[16*20480];      // NCH=20 (enc: Whh + Wih)
__device__ __align__(128) uint32_t g_d0B[16*20480];     // NCH=20 (dec step0: dWhh + dWih)
__device__ __align__(128) uint32_t g_dB[16*16384];      // NCH=16 (dec folded)
__device__ __align__(128) float g_Wcomb[768*256];       // reg fold temp
__device__ float g_bias_enc[1024], g_bias_dec[1024], g_bias_dec0[1024];
__device__ float g_regWT[256*64];
__device__ unsigned g_bar;

// ---------------- prep helpers ----------------
__device__ __forceinline__ uint32_t pack_split(float v0, float v1, int part) {
    __nv_bfloat16 h0 = __float2bfloat16(v0), h1 = __float2bfloat16(v1);
    if (part == 0)
        return (uint32_t)__bfloat16_as_ushort(h0) | ((uint32_t)__bfloat16_as_ushort(h1) << 16);
    __nv_bfloat16 l0 = __float2bfloat16(v0 - __bfloat162float(h0));
    __nv_bfloat16 l1 = __float2bfloat16(v1 - __bfloat162float(h1));
    return (uint32_t)__bfloat16_as_ushort(l0) | ((uint32_t)__bfloat16_as_ushort(l1) << 16);
}

__device__ __forceinline__ float gru_w(const float* Wih, const float* Whh,
                                       int sec, int j, int k) {
    if (k < 256) {
        if (sec == 0) return Whh[j*256 + k];
        if (sec == 1) return Whh[(256 + j)*256 + k];
        if (sec == 3) return Whh[(512 + j)*256 + k];
        return 0.f;
    } else {
        int f = k - 256;
        if (sec == 0) return Wih[j*64 + f];
        if (sec == 1) return Wih[(256 + j)*64 + f];
        if (sec == 2) return Wih[(512 + j)*64 + f];
        return 0.f;
    }
}

__global__ void k_fold(const float* __restrict__ dWih, const float* __restrict__ rW)
{
    int n = blockIdx.x;
    int k = threadIdx.x;
    float s = 0.f;
    #pragma unroll
    for (int f = 0; f < 64; f++) s += rW[f*256 + k] * dWih[n*64 + f];
    g_Wcomb[n*256 + k] = s;
}

__global__ void k_prep_frag(const float* __restrict__ eWih, const float* __restrict__ eWhh,
                            const float* __restrict__ dWih, const float* __restrict__ dWhh)
{
    const int stride = gridDim.x * blockDim.x;
    const int t0 = blockIdx.x * blockDim.x + threadIdx.x;

    for (int i = t0; i < 16*20480; i += stride) {
        int jt = i / 20480, rem = i % 20480;
        int part = rem / 10240; rem %= 10240;
        int ch = rem / 512;     rem %= 512;
        int ng = rem / 64;      rem %= 64;
        int lane = rem >> 1, r = rem & 1;
        int k  = ch*16 + (lane & 3)*2 + r*8;
        int nl = ng*8 + (lane >> 2);
        int sec = nl & 3, j = jt*16 + (nl >> 2);
        g_eB[i]  = pack_split(gru_w(eWih, eWhh, sec, j, k), gru_w(eWih, eWhh, sec, j, k+1), part);
        g_d0B[i] = pack_split(gru_w(dWih, dWhh, sec, j, k), gru_w(dWih, dWhh, sec, j, k+1), part);
    }

    for (int i = t0; i < 16*16384; i += stride) {
        int jt = i / 16384, rem = i % 16384;
        int part = rem / 8192; rem %= 8192;
        int ch = rem / 512;    rem %= 512;
        int ng = rem / 64;     rem %= 64;
        int lane = rem >> 1, r = rem & 1;
        int k  = ch*16 + (lane & 3)*2 + r*8;
        int nl = ng*8 + (lane >> 2);
        int sec = nl & 3, j = jt*16 + (nl >> 2);
        float v0, v1;
        if (sec == 3) {
            v0 = dWhh[(512 + j)*256 + k];
            v1 = dWhh[(512 + j)*256 + k + 1];
        } else {
            int n = sec*256 + j;
            v0 = g_Wcomb[n*256 + k]     + ((sec < 2) ? dWhh[n*256 + k]     : 0.f);
            v1 = g_Wcomb[n*256 + k + 1] + ((sec < 2) ? dWhh[n*256 + k + 1] : 0.f);
        }
        g_dB[i] = pack_split(v0, v1, part);
    }
}

__global__ void k_prep_x(const float* __restrict__ x)
{
    const int stride = gridDim.x * blockDim.x;
    for (int i = blockIdx.x * blockDim.x + threadIdx.x; i < 256*512*64; i += stride) {
        int t = i / (512*64); int rem = i - t*512*64;
        int m = rem >> 6, f = rem & 63;
        float v = x[(m*256 + t)*64 + f];
        __nv_bfloat16 hb = __float2bfloat16(v);
        g_Xh[i] = hb;
        g_Xl[i] = __float2bfloat16(v - __bfloat162float(hb));
    }
}

__global__ void k_prep_bias(const float* __restrict__ ebih, const float* __restrict__ ebhh,
                            const float* __restrict__ dWih,
                            const float* __restrict__ dbih, const float* __restrict__ dbhh,
                            const float* __restrict__ rW,   const float* __restrict__ rb)
{
    const int stride = gridDim.x * blockDim.x;
    const int t0 = blockIdx.x * blockDim.x + threadIdx.x;
    for (int i = t0; i < 256*64; i += stride) {
        int k = i >> 6, f = i & 63;
        g_regWT[i] = rW[f*256 + k];
    }
    for (int i = t0; i < 1024; i += stride) {
        int sec = i >> 8, j = i & 255;
        float be, bd0, bd;
        if (sec <= 1) {
            int n = sec*256 + j;
            be  = ebih[n] + ebhh[n];
            bd0 = dbih[n] + dbhh[n];
            float bc = dbih[n];
            for (int f = 0; f < 64; f++) bc += rb[f]*dWih[n*64 + f];
            bd = bc + dbhh[n];
        } else if (sec == 2) {
            int n = 512 + j;
            be = ebih[n]; bd0 = dbih[n];
            float bc = dbih[n];
            for (int f = 0; f < 64; f++) bc += rb[f]*dWih[n*64 + f];
            bd = bc;
        } else {
            int n = 512 + j;
            be = ebhh[n]; bd0 = dbhh[n]; bd = dbhh[n];
        }
        g_bias_enc[i] = be; g_bias_dec0[i] = bd0; g_bias_dec[i] = bd;
    }
}

__global__ void k_reset() { g_bar = 0u; }

// ---------------- persistent fused GRU recurrence ----------------
#define ASTRIDE 328                     // A smem row stride in bf16 (pad 8)
#define APS (64*ASTRIDE*2)              // 41984 bytes per precision part
#define SB_OFF   (2*APS)                // 83968
#define SHOLD_OFF (SB_OFF + 81920)      // 165888
#define SMEM_BYTES (SHOLD_OFF + 4096)   // 169984

#define MMA16816(d, a, b0, b1) \
    asm volatile("mma.sync.aligned.m16n8k16.row.col.f32.bf16.bf16.f32 " \
        "{%0,%1,%2,%3},{%4,%5,%6,%7},{%8,%9},{%0,%1,%2,%3};" \
        : "+f"((d)[0]), "+f"((d)[1]), "+f"((d)[2]), "+f"((d)[3]) \
        : "r"((a)[0]), "r"((a)[1]), "r"((a)[2]), "r"((a)[3]), "r"(b0), "r"(b1))

#define LDSM4(a, addr) \
    asm volatile("ldmatrix.sync.aligned.m8n8.x4.shared.b16 {%0,%1,%2,%3}, [%4];" \
        : "=r"((a)[0]), "=r"((a)[1]), "=r"((a)[2]), "=r"((a)[3]) : "r"(addr))

__device__ __forceinline__ void cp16(void* smem_dst, const void* gsrc) {
    uint32_t d = (uint32_t)__cvta_generic_to_shared(smem_dst);
    asm volatile("cp.async.ca.shared.global [%0], [%1], 16;" :: "r"(d), "l"(gsrc));
}
#define CP_COMMIT() asm volatile("cp.async.commit_group;" ::: "memory")
#define CP_WAIT(n)  asm volatile("cp.async.wait_group %0;" :: "n"(n) : "memory")

// A fragments via ldmatrix.x4; B via LDS.64 pairs.
template<int CH0, int CH1, int NCH>
__device__ __forceinline__ void mma_chunks(uint32_t aAddr0, const uint32_t* sBu,
                                           float acc[2][2][4], int wn, int lane)
{
    #pragma unroll 4
    for (int ch = CH0; ch < CH1; ch++) {
        uint32_t ah[2][4], al[2][4];
        #pragma unroll
        for (int mi = 0; mi < 2; mi++) {
            uint32_t ad = aAddr0 + mi*(16*ASTRIDE*2) + ch*32;
            LDSM4(ah[mi], ad);
            LDSM4(al[mi], ad + APS);
        }
        #pragma unroll
        for (int ni = 0; ni < 2; ni++) {
            const int ng = wn*2 + ni;
            const uint32_t* bp = sBu + ((ch*8 + ng)*32 + lane)*2;
            uint2 bh = *(const uint2*)bp;
            uint2 bl = *(const uint2*)(bp + NCH*512);
            #pragma unroll
            for (int mi = 0; mi < 2; mi++) {
                MMA16816(acc[mi][ni], ah[mi], bh.x, bh.y);
                MMA16816(acc[mi][ni], ah[mi], bl.x, bl.y);
                MMA16816(acc[mi][ni], al[mi], bh.x, bh.y);
            }
        }
    }
}

__global__ __launch_bounds__(256, 1) void k_persist(
    const __nv_bfloat16* __restrict__ Xh, const __nv_bfloat16* __restrict__ Xl,
    const uint4* __restrict__ eB, const uint4* __restrict__ d0B, const uint4* __restrict__ dB,
    const float* __restrict__ be, const float* __restrict__ bd0, const float* __restrict__ bd,
    float* __restrict__ Hdec,
    __nv_bfloat16* __restrict__ A0h, __nv_bfloat16* __restrict__ A0l,
    __nv_bfloat16* __restrict__ A1h, __nv_bfloat16* __restrict__ A1l)
{
    extern __shared__ char sm[];
    const int tid = threadIdx.x;
    const int bid = blockIdx.x;
    const int mt = bid & 7;
    const int jt = bid >> 3;
    const int m0 = mt*64;

    uint4* sA4h = (uint4*)sm;
    uint4* sA4l = (uint4*)(sm + APS);
    uint4* sB4  = (uint4*)(sm + SB_OFF);
    float* sHold = (float*)(sm + SHOLD_OFF);
    const uint32_t* sBu = (const uint32_t*)(sm + SB_OFF);

    const int lane = tid & 31;
    const int wid  = tid >> 5;
    const int wm = wid & 1, wn = wid >> 1;
    const int qr = lane >> 2, qp = lane & 3;

    const uint32_t sAu = (uint32_t)__cvta_generic_to_shared(sm);
    const uint32_t aAddr0 = sAu + ((wm*32 + (lane & 15))*ASTRIDE + (lane >> 4)*8)*2;

    for (int i = tid; i < 1024; i += 256) sHold[i] = 0.f;

    for (int s = 0; s < 256; s++) {
        // ---- B phase load (3 times total) ----
        if (s == 0 || s == 128 || s == 129) {
            const uint4* Bsrc;
            int nB;
            if (s == 0)        { Bsrc = eB  + (size_t)jt * (20*256); nB = 20*256; }
            else if (s == 128) { Bsrc = d0B + (size_t)jt * (20*256); nB = 20*256; }
            else               { Bsrc = dB  + (size_t)jt * (16*256); nB = 16*256; }
            for (int i = tid; i < nB; i += 256) sB4[i] = Bsrc[i];
        }

        // ---- A stage: cp.async double-buffer (group0: uint4 cols 0..15; group1: 16..31 + X) ----
        const uint4* Ah4 = (const uint4*)(((s - 1) & 1) ? A1h : A0h);
        const uint4* Al4 = (const uint4*)(((s - 1) & 1) ? A1l : A0l);
        if (s) {
            #pragma unroll
            for (int i = tid; i < 1024; i += 256) {
                int r = i >> 4, c = i & 15;
                cp16(&sA4h[r*41 + c], &Ah4[(m0 + r)*32 + c]);
                cp16(&sA4l[r*41 + c], &Al4[(m0 + r)*32 + c]);
            }
        } else {
            uint4 z = make_uint4(0, 0, 0, 0);
            #pragma unroll
            for (int i = tid; i < 1024; i += 256) {
                int r = i >> 4, c = i & 15;
                sA4h[r*41 + c] = z; sA4l[r*41 + c] = z;
            }
        }
        CP_COMMIT();
        if (s) {
            #pragma unroll
            for (int i = tid; i < 1024; i += 256) {
                int r = i >> 4, c = 16 + (i & 15);
                cp16(&sA4h[r*41 + c], &Ah4[(m0 + r)*32 + c]);
                cp16(&sA4l[r*41 + c], &Al4[(m0 + r)*32 + c]);
            }
        } else {
            uint4 z = make_uint4(0, 0, 0, 0);
            #pragma unroll
            for (int i = tid; i < 1024; i += 256) {
                int r = i >> 4, c = 16 + (i & 15);
                sA4h[r*41 + c] = z; sA4l[r*41 + c] = z;
            }
        }
        if (s <= 128) {
            int t = (s < 128) ? s : 127;
            const uint4* Xh4 = (const uint4*)(Xh + (size_t)t*NB*64);
            const uint4* Xl4 = (const uint4*)(Xl + (size_t)t*NB*64);
            #pragma unroll
            for (int i = tid; i < 512; i += 256) {
                int r = i >> 3, c = 32 + (i & 7);
                cp16(&sA4h[r*41 + c], &Xh4[(m0 + r)*8 + (c - 32)]);
                cp16(&sA4l[r*41 + c], &Xl4[(m0 + r)*8 + (c - 32)]);
            }
        }
        CP_COMMIT();

        // ---- 3-pass split-bf16 MMA, pipelined against the second cp.async group ----
        float acc[2][2][4];
        #pragma unroll
        for (int a = 0; a < 2; a++)
            #pragma unroll
            for (int b = 0; b < 2; b++)
                #pragma unroll
                for (int c = 0; c < 4; c++) acc[a][b][c] = 0.f;

        CP_WAIT(1);
        __syncthreads();
        if (s <= 128) mma_chunks<0, 8, 20>(aAddr0, sBu, acc, wn, lane);
        else          mma_chunks<0, 8, 16>(aAddr0, sBu, acc, wn, lane);
        CP_WAIT(0);
        __syncthreads();
        if (s <= 128) mma_chunks<8, 20, 20>(aAddr0, sBu, acc, wn, lane);
        else          mma_chunks<8, 16, 16>(aAddr0, sBu, acc, wn, lane);

        const float* bias = (s < 128) ? be : ((s == 128) ? bd0 : bd);

        // ---- fused GRU epilogue; h tile persists in sHold ----
        #pragma unroll
        for (int mi = 0; mi < 2; mi++) {
            #pragma unroll
            for (int ni = 0; ni < 2; ni++) {
                float d0 = acc[mi][ni][0], d1 = acc[mi][ni][1];
                float d2 = acc[mi][ni][2], d3 = acc[mi][ni][3];
                float e0 = __shfl_xor_sync(0xffffffffu, d0, 1);
                float e1 = __shfl_xor_sync(0xffffffffu, d1, 1);
                float e2 = __shfl_xor_sync(0xffffffffu, d2, 1);
                float e3 = __shfl_xor_sync(0xffffffffu, d3, 1);
                if ((qp & 1) == 0) {
                    const int jloc = wn*4 + ni*2 + (qp >> 1);
                    const int j = jt*16 + jloc;
                    const float b0 = bias[j], b1 = bias[256 + j];
                    const float b2 = bias[512 + j], b3 = bias[768 + j];
                    #pragma unroll
                    for (int hf = 0; hf < 2; hf++) {
                        const int mloc = wm*32 + mi*16 + qr + hf*8;
                        float ga = (hf ? d2 : d0) + b0;
                        float gb = (hf ? d3 : d1) + b1;
                        float gc = (hf ? e2 : e0) + b2;
                        float gd = (hf ? e3 : e1) + b3;
                        float rg = 1.f/(1.f + __expf(-ga));
                        float zg = 1.f/(1.f + __expf(-gb));
                        float nn = tanhf(fmaf(rg, gd, gc));
                        float hv = (1.f - zg)*nn + zg*sHold[mloc*16 + jloc];
                        sHold[mloc*16 + jloc] = hv;
                    }
                }
            }
        }
        __syncthreads();

        // ---- outputs: bf16 hi/lo A for next step; fp32 Hdec for decoder ----
        __nv_bfloat16* obh = (s & 1) ? A1h : A0h;
        __nv_bfloat16* obl = (s & 1) ? A1l : A0l;
        if (tid < 64) {
            int r = tid;
            union { uint4 v; ushort u[8]; } ph[2], pl[2];
            #pragma unroll
            for (int c = 0; c < 16; c++) {
                float f = sHold[r*16 + c];
                __nv_bfloat16 hb = __float2bfloat16(f);
                __nv_bfloat16 lb = __float2bfloat16(f - __bfloat162float(hb));
                ph[c >> 3].u[c & 7] = __bfloat16_as_ushort(hb);
                pl[c >> 3].u[c & 7] = __bfloat16_as_ushort(lb);
            }
            uint4* dh = (uint4*)(obh + (size_t)(m0 + r)*256 + jt*16);
            uint4* dl = (uint4*)(obl + (size_t)(m0 + r)*256 + jt*16);
            dh[0] = ph[0].v; dh[1] = ph[1].v;
            dl[0] = pl[0].v; dl[1] = pl[1].v;
        }
        if (s >= 128) {
            int r = tid >> 2, c = tid & 3;
            float4 v = make_float4(sHold[r*16 + c*4], sHold[r*16 + c*4 + 1],
                                   sHold[r*16 + c*4 + 2], sHold[r*16 + c*4 + 3]);
            *(float4*)&Hdec[(size_t)(s - 128)*NB*NH + (size_t)(m0 + r)*256 + jt*16 + c*4] = v;
        }
        __syncthreads();

        // ---- grid barrier (monotonic counter; reset per launch by k_reset) ----
        if (tid == 0) {
            __threadfence();
            atomicAdd(&g_bar, 1u);
            unsigned target = (unsigned)(s + 1) * NCTA;
            while (*(volatile unsigned*)&g_bar < target) {}
            __threadfence();
        }
        __syncthreads();
    }
}

// ---------------- final projection ----------------
__global__ __launch_bounds__(256) void k_out(const float* __restrict__ Hdec,
                                             const float* __restrict__ regWT,
                                             const float* __restrict__ rb,
                                             float* __restrict__ out)
{
    __shared__ float hs[32][260];
    const int tid = threadIdx.x;
    const int r0 = blockIdx.x * 32;
    #pragma unroll
    for (int i = 0; i < 8; i++) {
        int g = i*256 + tid; int row = g >> 6, kq = g & 63;
        *(float4*)&hs[row][kq*4] = *(const float4*)(Hdec + (size_t)(r0 + row)*256 + kq*4);
    }
    __syncthreads();
    const int row = tid >> 3;
    const int f0 = (tid & 7)*8;
    float acc[8];
    #pragma unroll
    for (int q = 0; q < 8; q++) acc[q] = rb[f0 + q];
    for (int k = 0; k < 256; k++) {
        float hvv = hs[row][k];
        float4 w0 = *(const float4*)(regWT + k*64 + f0);
        float4 w1 = *(const float4*)(regWT + k*64 + f0 + 4);
        acc[0] += hvv*w0.x; acc[1] += hvv*w0.y; acc[2] += hvv*w0.z; acc[3] += hvv*w0.w;
        acc[4] += hvv*w1.x; acc[5] += hvv*w1.y; acc[6] += hvv*w1.z; acc[7] += hvv*w1.w;
    }
    int rr = r0 + row;
    int b = rr & 511;
    int t = rr >> 9;
    float* o = out + ((size_t)b*128 + t)*64 + f0;
    #pragma unroll
    for (int q = 0; q < 8; q++) o[q] = acc[q];
}

// ---------------- launch ----------------
extern "C" void kernel_launch(void* const* d_in, const int* in_sizes, int n_in,
                              void* d_out, int out_size)
{
    (void)in_sizes; (void)n_in; (void)out_size;
    const float* x    = (const float*)d_in[0];
    const float* eWih = (const float*)d_in[1];
    const float* eWhh = (const float*)d_in[2];
    const float* ebih = (const float*)d_in[3];
    const float* ebhh = (const float*)d_in[4];
    const float* dWih = (const float*)d_in[5];
    const float* dWhh = (const float*)d_in[6];
    const float* dbih = (const float*)d_in[7];
    const float* dbhh = (const float*)d_in[8];
    const float* rW   = (const float*)d_in[9];
    const float* rb   = (const float*)d_in[10];
    float* out = (float*)d_out;

    float *pHdec, *pBe, *pBd, *pBd0, *pWT;
    __nv_bfloat16 *pA0h, *pA0l, *pA1h, *pA1l, *pXh, *pXl;
    uint32_t *peB, *pd0B, *pdB;
    cudaGetSymbolAddress((void**)&pHdec, g_Hdec);
    cudaGetSymbolAddress((void**)&pA0h, g_A0h);
    cudaGetSymbolAddress((void**)&pA0l, g_A0l);
    cudaGetSymbolAddress((void**)&pA1h, g_A1h);
    cudaGetSymbolAddress((void**)&pA1l, g_A1l);
    cudaGetSymbolAddress((void**)&pXh, g_Xh);
    cudaGetSymbolAddress((void**)&pXl, g_Xl);
    cudaGetSymbolAddress((void**)&peB, g_eB);
    cudaGetSymbolAddress((void**)&pd0B, g_d0B);
    cudaGetSymbolAddress((void**)&pdB, g_dB);
    cudaGetSymbolAddress((void**)&pBe, g_bias_enc);
    cudaGetSymbolAddress((void**)&pBd, g_bias_dec);
    cudaGetSymbolAddress((void**)&pBd0, g_bias_dec0);
    cudaGetSymbolAddress((void**)&pWT, g_regWT);

    cudaFuncSetAttribute(k_persist, cudaFuncAttributeMaxDynamicSharedMemorySize, SMEM_BYTES);

    k_fold<<<768, 256>>>(dWih, rW);
    k_prep_frag<<<512, 256>>>(eWih, eWhh, dWih, dWhh);
    k_prep_x<<<2048, 256>>>(x);
    k_prep_bias<<<128, 256>>>(ebih, ebhh, dWih, dbih, dbhh, rW, rb);
    k_reset<<<1, 1>>>();

    k_persist<<<NCTA, 256, SMEM_BYTES>>>(
        pXh, pXl,
        (const uint4*)peB, (const uint4*)pd0B, (const uint4*)pdB,
        pBe, pBd0, pBd,
        pHdec, pA0h, pA0l, pA1h, pA1l);

    k_out<<<(NB*NT)/32, 256>>>(pHdec, pWT, rb, out);
}

// round 11
// speedup vs baseline: 1.7156x; 1.1604x over previous
#include <cuda_runtime.h>
#include <cuda_bf16.h>
#include <cuda_fp16.h>
#include <cstdint>

#define NB 512
#define NH 256
#define NT 128
#define NCTA 128

// ---------------- device scratch ----------------
__device__ __align__(128) float g_Hdec[NT*NB*NH];
__device__ __align__(128) __half g_A0[NB*NH], g_A1[NB*NH];     // h as single fp16
__device__ __align__(128) __half g_Xf[256*NB*64];              // x as single fp16
// B fragment order per jt: [part(2: hi,lo)][chunk(NCH)][ng(8)][lane(32)][reg(2)] u32 (fp16x2)
__device__ __align__(128) uint32_t g_eB[16*20480];      // NCH=20 (enc: Whh + Wih)
__device__ __align__(128) uint32_t g_d0B[16*20480];     // NCH=20 (dec step0: dWhh + dWih)
__device__ __align__(128) uint32_t g_dB[16*16384];      // NCH=16 (dec folded)
__device__ __align__(128) float g_Wcomb[768*256];       // reg fold temp
__device__ float g_bias_enc[1024], g_bias_dec[1024], g_bias_dec0[1024];
__device__ float g_regWT[256*64];
__device__ unsigned g_bar;

// ---------------- prep helpers ----------------
__device__ __forceinline__ uint32_t pack_split_f16(float v0, float v1, int part) {
    __half h0 = __float2half(v0), h1 = __float2half(v1);
    if (part == 0)
        return (uint32_t)__half_as_ushort(h0) | ((uint32_t)__half_as_ushort(h1) << 16);
    __half l0 = __float2half(v0 - __half2float(h0));
    __half l1 = __float2half(v1 - __half2float(h1));
    return (uint32_t)__half_as_ushort(l0) | ((uint32_t)__half_as_ushort(l1) << 16);
}

__device__ __forceinline__ float gru_w(const float* Wih, const float* Whh,
                                       int sec, int j, int k) {
    if (k < 256) {
        if (sec == 0) return Whh[j*256 + k];
        if (sec == 1) return Whh[(256 + j)*256 + k];
        if (sec == 3) return Whh[(512 + j)*256 + k];
        return 0.f;
    } else {
        int f = k - 256;
        if (sec == 0) return Wih[j*64 + f];
        if (sec == 1) return Wih[(256 + j)*64 + f];
        if (sec == 2) return Wih[(512 + j)*64 + f];
        return 0.f;
    }
}

__global__ void k_fold(const float* __restrict__ dWih, const float* __restrict__ rW)
{
    int n = blockIdx.x;
    int k = threadIdx.x;
    float s = 0.f;
    #pragma unroll
    for (int f = 0; f < 64; f++) s += rW[f*256 + k] * dWih[n*64 + f];
    g_Wcomb[n*256 + k] = s;
}

__global__ void k_prep_frag(const float* __restrict__ eWih, const float* __restrict__ eWhh,
                            const float* __restrict__ dWih, const float* __restrict__ dWhh)
{
    const int stride = gridDim.x * blockDim.x;
    const int t0 = blockIdx.x * blockDim.x + threadIdx.x;

    for (int i = t0; i < 16*20480; i += stride) {
        int jt = i / 20480, rem = i % 20480;
        int part = rem / 10240; rem %= 10240;
        int ch = rem / 512;     rem %= 512;
        int ng = rem / 64;      rem %= 64;
        int lane = rem >> 1, r = rem & 1;
        int k  = ch*16 + (lane & 3)*2 + r*8;
        int nl = ng*8 + (lane >> 2);
        int sec = nl & 3, j = jt*16 + (nl >> 2);
        g_eB[i]  = pack_split_f16(gru_w(eWih, eWhh, sec, j, k), gru_w(eWih, eWhh, sec, j, k+1), part);
        g_d0B[i] = pack_split_f16(gru_w(dWih, dWhh, sec, j, k), gru_w(dWih, dWhh, sec, j, k+1), part);
    }

    for (int i = t0; i < 16*16384; i += stride) {
        int jt = i / 16384, rem = i % 16384;
        int part = rem / 8192; rem %= 8192;
        int ch = rem / 512;    rem %= 512;
        int ng = rem / 64;     rem %= 64;
        int lane = rem >> 1, r = rem & 1;
        int k  = ch*16 + (lane & 3)*2 + r*8;
        int nl = ng*8 + (lane >> 2);
        int sec = nl & 3, j = jt*16 + (nl >> 2);
        float v0, v1;
        if (sec == 3) {
            v0 = dWhh[(512 + j)*256 + k];
            v1 = dWhh[(512 + j)*256 + k + 1];
        } else {
            int n = sec*256 + j;
            v0 = g_Wcomb[n*256 + k]     + ((sec < 2) ? dWhh[n*256 + k]     : 0.f);
            v1 = g_Wcomb[n*256 + k + 1] + ((sec < 2) ? dWhh[n*256 + k + 1] : 0.f);
        }
        g_dB[i] = pack_split_f16(v0, v1, part);
    }
}

__global__ void k_prep_x(const float* __restrict__ x)
{
    const int stride = gridDim.x * blockDim.x;
    for (int i = blockIdx.x * blockDim.x + threadIdx.x; i < 256*512*64; i += stride) {
        int t = i / (512*64); int rem = i - t*512*64;
        int m = rem >> 6, f = rem & 63;
        g_Xf[i] = __float2half(x[(m*256 + t)*64 + f]);
    }
}

__global__ void k_prep_bias(const float* __restrict__ ebih, const float* __restrict__ ebhh,
                            const float* __restrict__ dWih,
                            const float* __restrict__ dbih, const float* __restrict__ dbhh,
                            const float* __restrict__ rW,   const float* __restrict__ rb)
{
    const int stride = gridDim.x * blockDim.x;
    const int t0 = blockIdx.x * blockDim.x + threadIdx.x;
    for (int i = t0; i < 256*64; i += stride) {
        int k = i >> 6, f = i & 63;
        g_regWT[i] = rW[f*256 + k];
    }
    for (int i = t0; i < 1024; i += stride) {
        int sec = i >> 8, j = i & 255;
        float be, bd0, bd;
        if (sec <= 1) {
            int n = sec*256 + j;
            be  = ebih[n] + ebhh[n];
            bd0 = dbih[n] + dbhh[n];
            float bc = dbih[n];
            for (int f = 0; f < 64; f++) bc += rb[f]*dWih[n*64 + f];
            bd = bc + dbhh[n];
        } else if (sec == 2) {
            int n = 512 + j;
            be = ebih[n]; bd0 = dbih[n];
            float bc = dbih[n];
            for (int f = 0; f < 64; f++) bc += rb[f]*dWih[n*64 + f];
            bd = bc;
        } else {
            int n = 512 + j;
            be = ebhh[n]; bd0 = dbhh[n]; bd = dbhh[n];
        }
        g_bias_enc[i] = be; g_bias_dec0[i] = bd0; g_bias_dec[i] = bd;
    }
}

__global__ void k_reset() { g_bar = 0u; }

// ---------------- persistent fused GRU recurrence ----------------
#define ASTRIDE 328                     // A smem row stride in fp16 (pad 8)
#define APS (64*ASTRIDE*2)              // 41984 bytes: single A buffer
#define SB_OFF   APS                    // 41984
#define SHOLD_OFF (SB_OFF + 81920)      // 123904
#define SMEM_BYTES (SHOLD_OFF + 4096)   // 128000

#define MMA16816(d, a, b0, b1) \
    asm volatile("mma.sync.aligned.m16n8k16.row.col.f32.f16.f16.f32 " \
        "{%0,%1,%2,%3},{%4,%5,%6,%7},{%8,%9},{%0,%1,%2,%3};" \
        : "+f"((d)[0]), "+f"((d)[1]), "+f"((d)[2]), "+f"((d)[3]) \
        : "r"((a)[0]), "r"((a)[1]), "r"((a)[2]), "r"((a)[3]), "r"(b0), "r"(b1))

#define LDSM4(a, addr) \
    asm volatile("ldmatrix.sync.aligned.m8n8.x4.shared.b16 {%0,%1,%2,%3}, [%4];" \
        : "=r"((a)[0]), "=r"((a)[1]), "=r"((a)[2]), "=r"((a)[3]) : "r"(addr))

__device__ __forceinline__ void cp16(void* smem_dst, const void* gsrc) {
    uint32_t d = (uint32_t)__cvta_generic_to_shared(smem_dst);
    asm volatile("cp.async.ca.shared.global [%0], [%1], 16;" :: "r"(d), "l"(gsrc));
}
#define CP_COMMIT() asm volatile("cp.async.commit_group;" ::: "memory")
#define CP_WAIT(n)  asm volatile("cp.async.wait_group %0;" :: "n"(n) : "memory")

// A fragments via ldmatrix.x4 (single-precision-part A); B hi+lo via LDS.64.
template<int CH0, int CH1, int NCH>
__device__ __forceinline__ void mma_chunks(uint32_t aAddr0, const uint32_t* sBu,
                                           float acc[2][2][4], int wn, int lane)
{
    #pragma unroll 4
    for (int ch = CH0; ch < CH1; ch++) {
        uint32_t av[2][4];
        #pragma unroll
        for (int mi = 0; mi < 2; mi++) {
            LDSM4(av[mi], aAddr0 + mi*(16*ASTRIDE*2) + ch*32);
        }
        #pragma unroll
        for (int ni = 0; ni < 2; ni++) {
            const int ng = wn*2 + ni;
            const uint32_t* bp = sBu + ((ch*8 + ng)*32 + lane)*2;
            uint2 bh = *(const uint2*)bp;
            uint2 bl = *(const uint2*)(bp + NCH*512);
            #pragma unroll
            for (int mi = 0; mi < 2; mi++) {
                MMA16816(acc[mi][ni], av[mi], bh.x, bh.y);
                MMA16816(acc[mi][ni], av[mi], bl.x, bl.y);
            }
        }
    }
}

__global__ __launch_bounds__(256, 1) void k_persist(
    const __half* __restrict__ Xf,
    const uint4* __restrict__ eB, const uint4* __restrict__ d0B, const uint4* __restrict__ dB,
    const float* __restrict__ be, const float* __restrict__ bd0, const float* __restrict__ bd,
    float* __restrict__ Hdec,
    __half* __restrict__ A0, __half* __restrict__ A1)
{
    extern __shared__ char sm[];
    const int tid = threadIdx.x;
    const int bid = blockIdx.x;
    const int mt = bid & 7;
    const int jt = bid >> 3;
    const int m0 = mt*64;

    uint4* sA4 = (uint4*)sm;
    uint4* sB4 = (uint4*)(sm + SB_OFF);
    float* sHold = (float*)(sm + SHOLD_OFF);
    const uint32_t* sBu = (const uint32_t*)(sm + SB_OFF);

    const int lane = tid & 31;
    const int wid  = tid >> 5;
    const int wm = wid & 1, wn = wid >> 1;
    const int qr = lane >> 2, qp = lane & 3;

    const uint32_t sAu = (uint32_t)__cvta_generic_to_shared(sm);
    const uint32_t aAddr0 = sAu + ((wm*32 + (lane & 15))*ASTRIDE + (lane >> 4)*8)*2;

    for (int i = tid; i < 1024; i += 256) sHold[i] = 0.f;

    for (int s = 0; s < 256; s++) {
        // ---- B phase load (3 times total) ----
        if (s == 0 || s == 128 || s == 129) {
            const uint4* Bsrc;
            int nB;
            if (s == 0)        { Bsrc = eB  + (size_t)jt * (20*256); nB = 20*256; }
            else if (s == 128) { Bsrc = d0B + (size_t)jt * (20*256); nB = 20*256; }
            else               { Bsrc = dB  + (size_t)jt * (16*256); nB = 16*256; }
            for (int i = tid; i < nB; i += 256) sB4[i] = Bsrc[i];
        }

        // ---- A stage: cp.async two groups (group0: uint4 cols 0..15; group1: 16..31 + X) ----
        const uint4* A4 = (const uint4*)(((s - 1) & 1) ? A1 : A0);
        if (s) {
            #pragma unroll
            for (int i = tid; i < 1024; i += 256) {
                int r = i >> 4, c = i & 15;
                cp16(&sA4[r*41 + c], &A4[(m0 + r)*32 + c]);
            }
        } else {
            uint4 z = make_uint4(0, 0, 0, 0);
            #pragma unroll
            for (int i = tid; i < 1024; i += 256) {
                int r = i >> 4, c = i & 15;
                sA4[r*41 + c] = z;
            }
        }
        CP_COMMIT();
        if (s) {
            #pragma unroll
            for (int i = tid; i < 1024; i += 256) {
                int r = i >> 4, c = 16 + (i & 15);
                cp16(&sA4[r*41 + c], &A4[(m0 + r)*32 + c]);
            }
        } else {
            uint4 z = make_uint4(0, 0, 0, 0);
            #pragma unroll
            for (int i = tid; i < 1024; i += 256) {
                int r = i >> 4, c = 16 + (i & 15);
                sA4[r*41 + c] = z;
            }
        }
        if (s <= 128) {
            int t = (s < 128) ? s : 127;
            const uint4* X4 = (const uint4*)(Xf + (size_t)t*NB*64);
            #pragma unroll
            for (int i = tid; i < 512; i += 256) {
                int r = i >> 3, c = 32 + (i & 7);
                cp16(&sA4[r*41 + c], &X4[(m0 + r)*8 + (c - 32)]);
            }
        }
        CP_COMMIT();

        // ---- 2-pass fp16 MMA (A single, B hi+lo), pipelined against group1 ----
        float acc[2][2][4];
        #pragma unroll
        for (int a = 0; a < 2; a++)
            #pragma unroll
            for (int b = 0; b < 2; b++)
                #pragma unroll
                for (int c = 0; c < 4; c++) acc[a][b][c] = 0.f;

        CP_WAIT(1);
        __syncthreads();
        if (s <= 128) mma_chunks<0, 8, 20>(aAddr0, sBu, acc, wn, lane);
        else          mma_chunks<0, 8, 16>(aAddr0, sBu, acc, wn, lane);
        CP_WAIT(0);
        __syncthreads();
        if (s <= 128) mma_chunks<8, 20, 20>(aAddr0, sBu, acc, wn, lane);
        else          mma_chunks<8, 16, 16>(aAddr0, sBu, acc, wn, lane);

        const float* bias = (s < 128) ? be : ((s == 128) ? bd0 : bd);

        // ---- fused GRU epilogue; h tile persists in sHold ----
        #pragma unroll
        for (int mi = 0; mi < 2; mi++) {
            #pragma unroll
            for (int ni = 0; ni < 2; ni++) {
                float d0 = acc[mi][ni][0], d1 = acc[mi][ni][1];
                float d2 = acc[mi][ni][2], d3 = acc[mi][ni][3];
                float e0 = __shfl_xor_sync(0xffffffffu, d0, 1);
                float e1 = __shfl_xor_sync(0xffffffffu, d1, 1);
                float e2 = __shfl_xor_sync(0xffffffffu, d2, 1);
                float e3 = __shfl_xor_sync(0xffffffffu, d3, 1);
                if ((qp & 1) == 0) {
                    const int jloc = wn*4 + ni*2 + (qp >> 1);
                    const int j = jt*16 + jloc;
                    const float b0 = bias[j], b1 = bias[256 + j];
                    const float b2 = bias[512 + j], b3 = bias[768 + j];
                    #pragma unroll
                    for (int hf = 0; hf < 2; hf++) {
                        const int mloc = wm*32 + mi*16 + qr + hf*8;
                        float ga = (hf ? d2 : d0) + b0;
                        float gb = (hf ? d3 : d1) + b1;
                        float gc = (hf ? e2 : e0) + b2;
                        float gd = (hf ? e3 : e1) + b3;
                        float rg = 1.f/(1.f + __expf(-ga));
                        float zg = 1.f/(1.f + __expf(-gb));
                        float nn = tanhf(fmaf(rg, gd, gc));
                        float hv = (1.f - zg)*nn + zg*sHold[mloc*16 + jloc];
                        sHold[mloc*16 + jloc] = hv;
                    }
                }
            }
        }
        __syncthreads();

        // ---- outputs: fp16 A for next step; fp32 Hdec for decoder ----
        __half* ob = (s & 1) ? A1 : A0;
        if (tid < 64) {
            int r = tid;
            union { uint4 v; ushort u[8]; } ph[2];
            #pragma unroll
            for (int c = 0; c < 16; c++) {
                ph[c >> 3].u[c & 7] = __half_as_ushort(__float2half(sHold[r*16 + c]));
            }
            uint4* dh = (uint4*)(ob + (size_t)(m0 + r)*256 + jt*16);
            dh[0] = ph[0].v; dh[1] = ph[1].v;
        }
        if (s >= 128) {
            int r = tid >> 2, c = tid & 3;
            float4 v = make_float4(sHold[r*16 + c*4], sHold[r*16 + c*4 + 1],
                                   sHold[r*16 + c*4 + 2], sHold[r*16 + c*4 + 3]);
            *(float4*)&Hdec[(size_t)(s - 128)*NB*NH + (size_t)(m0 + r)*256 + jt*16 + c*4] = v;
        }
        __syncthreads();

        // ---- grid barrier (monotonic counter; reset per launch by k_reset) ----
        if (tid == 0) {
            __threadfence();
            atomicAdd(&g_bar, 1u);
            unsigned target = (unsigned)(s + 1) * NCTA;
            while (*(volatile unsigned*)&g_bar < target) {}
            __threadfence();
        }
        __syncthreads();
    }
}

// ---------------- final projection ----------------
__global__ __launch_bounds__(256) void k_out(const float* __restrict__ Hdec,
                                             const float* __restrict__ regWT,
                                             const float* __restrict__ rb,
                                             float* __restrict__ out)
{
    __shared__ float hs[32][260];
    const int tid = threadIdx.x;
    const int r0 = blockIdx.x * 32;
    #pragma unroll
    for (int i = 0; i < 8; i++) {
        int g = i*256 + tid; int row = g >> 6, kq = g & 63;
        *(float4*)&hs[row][kq*4] = *(const float4*)(Hdec + (size_t)(r0 + row)*256 + kq*4);
    }
    __syncthreads();
    const int row = tid >> 3;
    const int f0 = (tid & 7)*8;
    float acc[8];
    #pragma unroll
    for (int q = 0; q < 8; q++) acc[q] = rb[f0 + q];
    for (int k = 0; k < 256; k++) {
        float hvv = hs[row][k];
        float4 w0 = *(const float4*)(regWT + k*64 + f0);
        float4 w1 = *(const float4*)(regWT + k*64 + f0 + 4);
        acc[0] += hvv*w0.x; acc[1] += hvv*w0.y; acc[2] += hvv*w0.z; acc[3] += hvv*w0.w;
        acc[4] += hvv*w1.x; acc[5] += hvv*w1.y; acc[6] += hvv*w1.z; acc[7] += hvv*w1.w;
    }
    int rr = r0 + row;
    int b = rr & 511;
    int t = rr >> 9;
    float* o = out + ((size_t)b*128 + t)*64 + f0;
    #pragma unroll
    for (int q = 0; q < 8; q++) o[q] = acc[q];
}

// ---------------- launch ----------------
extern "C" void kernel_launch(void* const* d_in, const int* in_sizes, int n_in,
                              void* d_out, int out_size)
{
    (void)in_sizes; (void)n_in; (void)out_size;
    const float* x    = (const float*)d_in[0];
    const float* eWih = (const float*)d_in[1];
    const float* eWhh = (const float*)d_in[2];
    const float* ebih = (const float*)d_in[3];
    const float* ebhh = (const float*)d_in[4];
    const float* dWih = (const float*)d_in[5];
    const float* dWhh = (const float*)d_in[6];
    const float* dbih = (const float*)d_in[7];
    const float* dbhh = (const float*)d_in[8];
    const float* rW   = (const float*)d_in[9];
    const float* rb   = (const float*)d_in[10];
    float* out = (float*)d_out;

    float *pHdec, *pBe, *pBd, *pBd0, *pWT;
    __half *pA0, *pA1, *pXf;
    uint32_t *peB, *pd0B, *pdB;
    cudaGetSymbolAddress((void**)&pHdec, g_Hdec);
    cudaGetSymbolAddress((void**)&pA0, g_A0);
    cudaGetSymbolAddress((void**)&pA1, g_A1);
    cudaGetSymbolAddress((void**)&pXf, g_Xf);
    cudaGetSymbolAddress((void**)&peB, g_eB);
    cudaGetSymbolAddress((void**)&pd0B, g_d0B);
    cudaGetSymbolAddress((void**)&pdB, g_dB);
    cudaGetSymbolAddress((void**)&pBe, g_bias_enc);
    cudaGetSymbolAddress((void**)&pBd, g_bias_dec);
    cudaGetSymbolAddress((void**)&pBd0, g_bias_dec0);
    cudaGetSymbolAddress((void**)&pWT, g_regWT);

    cudaFuncSetAttribute(k_persist, cudaFuncAttributeMaxDynamicSharedMemorySize, SMEM_BYTES);

    k_fold<<<768, 256>>>(dWih, rW);
    k_prep_frag<<<512, 256>>>(eWih, eWhh, dWih, dWhh);
    k_prep_x<<<2048, 256>>>(x);
    k_prep_bias<<<128, 256>>>(ebih, ebhh, dWih, dbih, dbhh, rW, rb);
    k_reset<<<1, 1>>>();

    k_persist<<<NCTA, 256, SMEM_BYTES>>>(
        pXf,
        (const uint4*)peB, (const uint4*)pd0B, (const uint4*)pdB,
        pBe, pBd0, pBd,
        pHdec, pA0, pA1);

    k_out<<<(NB*NT)/32, 256>>>(pHdec, pWT, rb, out);
}